// round 13
// baseline (speedup 1.0000x reference)
#include <cuda_runtime.h>
#include <cuda_bf16.h>
#include <cstdint>

// EngramMemory: rolling-hash n-gram gather — full-TMA data path (R12).
//
// tokens: (4, 4096) int32, tables: (8, 2048, 256) f32, out: (4, 4096, 2048) f32
// out[p][part*256 + d] = tables[part][h(part,p)][d]
//   h = fold over order-(2+oi) n-gram: h = (h*1000003 + tok + seed) & 2047,
//   seed = 1337 + 97*(2+oi) + 17*head, left zero-padded. All math fits in u32.
//
// R12: four direct-gather configs converged at ~26.5us with no pipe >63% --
// a per-wavefront L1TEX/LSU structural ceiling. This version moves ALL data
// through the TMA bulk engine instead:
//   - 64 threads/CTA issue 64x cp.async.bulk (1 KB table row -> smem staging,
//     laid out as the output block), mbarrier expect_tx 64 KB.
//   - after the mbarrier flips, one thread issues a single 64 KB
//     cp.async.bulk smem -> gmem (the CTA's 8 output rows are contiguous).
// Zero L1TEX wavefronts, zero in-warp load-latency exposure.

namespace {
constexpr int B = 4;
constexpr int S = 4096;
constexpr int NUM_BUCKETS = 2048;
constexpr int HEAD_DIM = 256;
constexpr int PARTS = 8;                         // 2 orders * 4 heads
constexpr int ROWS = 8;                          // output rows per CTA
constexpr int ROW_BYTES = HEAD_DIM * 4;          // 1 KB per (part) row
constexpr int OUT_ROW_BYTES = PARTS * ROW_BYTES; // 8 KB per (b,s) row
constexpr int STAGE_BYTES = ROWS * OUT_ROW_BYTES; // 64 KB per CTA
constexpr int THREADS = 128;
constexpr unsigned PRIME = 1000003u;

// smem: [0,8) mbarrier | [1024, 1024+64K) staging
constexpr int SM_MBAR  = 0;
constexpr int SM_STAGE = 1024;
constexpr int SMEM_TOTAL = SM_STAGE + STAGE_BYTES;   // 66560 B -> 3 CTAs/SM

__device__ __forceinline__ uint32_t smem_u32(const void* p) {
    uint32_t a;
    asm("{ .reg .u64 t; cvta.to.shared.u64 t, %1; cvt.u32.u64 %0, t; }"
        : "=r"(a) : "l"(p));
    return a;
}

__global__ __launch_bounds__(THREADS, 3)
void engram_tma_kernel(const int*   __restrict__ tokens,
                       const float* __restrict__ tables,
                       float*       __restrict__ out) {
    extern __shared__ char smem[];
    const uint32_t smem_base = smem_u32(smem);
    const uint32_t mbar = smem_base + SM_MBAR;
    const int tid  = threadIdx.x;
    const int row0 = blockIdx.x * ROWS;      // base bs index

    if (tid == 0) {
        asm volatile("mbarrier.init.shared.b64 [%0], 1;" :: "r"(mbar) : "memory");
        asm volatile("mbarrier.arrive.expect_tx.shared.b64 _, [%0], %1;"
                     :: "r"(mbar), "r"((unsigned)STAGE_BYTES) : "memory");
    }
    __syncthreads();   // mbarrier init/expect visible before any copy lands

    // ---- Hash + gather issue: one (row, part) per thread ------------------
    if (tid < ROWS * PARTS) {
        const int r    = tid >> 3;
        const int part = tid & 7;
        const int bs   = row0 + r;
        const int b    = bs >> 12;           // / 4096
        const int s    = bs & (S - 1);       // % 4096
        const int oi    = part >> 2;
        const int head  = part & 3;
        const int order = 2 + oi;
        const unsigned seed = 1337u + 97u * (unsigned)order + 17u * (unsigned)head;
        unsigned h = 0u;
        #pragma unroll 3
        for (int i = 0; i < order; i++) {
            const int pos = s - order + 1 + i;
            unsigned tok = 0u;
            if (pos >= 0) tok = (unsigned)__ldg(tokens + b * S + pos);
            h = (h * PRIME + tok + seed) & (NUM_BUCKETS - 1);
        }

        const char* gsrc = reinterpret_cast<const char*>(tables) +
                           ((size_t)part * NUM_BUCKETS + h) * ROW_BYTES;
        const uint32_t sdst = smem_base + SM_STAGE +
                              (r * PARTS + part) * ROW_BYTES;
        asm volatile(
            "cp.async.bulk.shared::cta.global.mbarrier::complete_tx::bytes "
            "[%0], [%1], %2, [%3];"
            :: "r"(sdst), "l"(gsrc), "r"((unsigned)ROW_BYTES), "r"(mbar)
            : "memory");
    }

    // ---- Wait for all 64 row fills ----------------------------------------
    {
        uint32_t done;
        asm volatile(
            "{\n\t.reg .pred p;\n\t"
            "mbarrier.try_wait.parity.acquire.cta.shared::cta.b64 p, [%1], 0;\n\t"
            "selp.b32 %0, 1, 0, p;\n\t}"
            : "=r"(done) : "r"(mbar) : "memory");
        while (!done) {
            asm volatile(
                "{\n\t.reg .pred p;\n\t"
                "mbarrier.try_wait.parity.acquire.cta.shared::cta.b64 p, [%1], 0, 0x989680;\n\t"
                "selp.b32 %0, 1, 0, p;\n\t}"
                : "=r"(done) : "r"(mbar) : "memory");
        }
    }

    // ---- One 64 KB bulk store: staging -> contiguous output block ---------
    if (tid == 0) {
        char* gdst = reinterpret_cast<char*>(out) + (size_t)row0 * OUT_ROW_BYTES;
        asm volatile(
            "cp.async.bulk.global.shared::cta.bulk_group [%0], [%1], %2;"
            :: "l"(gdst), "r"(smem_base + SM_STAGE), "r"((unsigned)STAGE_BYTES)
            : "memory");
        asm volatile("cp.async.bulk.commit_group;" ::: "memory");
        asm volatile("cp.async.bulk.wait_group 0;" ::: "memory");
    }
}
} // namespace

extern "C" void kernel_launch(void* const* d_in, const int* in_sizes, int n_in,
                              void* d_out, int out_size) {
    // Resolve input order by element count: tokens = 16384, tables = 4194304.
    int ti = 0, wi = 1;
    if (n_in >= 2 && in_sizes[0] > in_sizes[1]) { ti = 1; wi = 0; }
    const int*   tokens = (const int*)d_in[ti];
    const float* tables = (const float*)d_in[wi];
    float*       out    = (float*)d_out;

    cudaFuncSetAttribute(engram_tma_kernel,
                         cudaFuncAttributeMaxDynamicSharedMemorySize, SMEM_TOTAL);
    engram_tma_kernel<<<(B * S) / ROWS, THREADS, SMEM_TOTAL>>>(tokens, tables, out);
}